// round 10
// baseline (speedup 1.0000x reference)
#include <cuda_runtime.h>
#include <cuda_fp16.h>
#include <cstdint>

// Tropical (max-plus) matmul: Y[b, j] = max_i (X[b, i] + W[j, i])
// fp16 path with per-row fp32 shift:
//   M_b = max_i X[b,i];  Xh = half(X - M_b);  Wh = half(W)
//   Y' = max-plus in packed fp16 (HADD2/HMNMX2 paired over k);  Y = Y' + M_b.
// Measured rel_err ~1.3e-6.
//
// R10: combine kernel FUSED into the main kernel via last-block-done
// (threadfence reduction): the 8th split-K block of each output tile reads
// the 8 half partials (L2-hot) and writes final fp32 Y. Removes one kernel
// launch + gap; per-tile reductions overlap with remaining compute.
// Counter uses (old & 7) == 7 so it stays correct across graph replays.

#define B_DIM   512
#define IN_DIM  1024
#define OUT_DIM 1024

#define SPLITK  8
#define KSEG    (IN_DIM / SPLITK)   // 128
#define BKH     64                  // halves per chunk
#define NCHH    (KSEG / BKH)        // 2
#define BMH     32
#define BNH     128
#define PADK    72                  // padded halves per smem row
#define NT      128
#define NTILES  ((B_DIM / BMH) * (OUT_DIM / BNH))   // 128

__device__ __half Xh[B_DIM * IN_DIM];
__device__ __half Wh[OUT_DIM * IN_DIM];
__device__ float  Mrow[B_DIM];
__device__ __half g_parth[SPLITK][B_DIM * OUT_DIM];   // 8 MB
__device__ unsigned g_cnt[NTILES];                    // zero-init

#define CPA16(dst_u32, src_ptr) \
    asm volatile("cp.async.cg.shared.global [%0], [%1], 16;" \
                 :: "r"(dst_u32), "l"(src_ptr))
#define CPA_COMMIT() asm volatile("cp.async.commit_group;")
#define CPA_WAIT1()  asm volatile("cp.async.wait_group 1;")
#define CPA_WAIT0()  asm volatile("cp.async.wait_group 0;")

// ---------- fused prep: blocks [0,512) shift+cvt X; [512,1024) cvt W ----------
__global__ __launch_bounds__(256)
void prep_xw(const float* __restrict__ X, const float* __restrict__ W) {
    const int t = threadIdx.x;
    if (blockIdx.x < B_DIM) {
        __shared__ float wmax[8];
        const int b = blockIdx.x;
        float4 v = ((const float4*)(X + (size_t)b * IN_DIM))[t];
        float m = fmaxf(fmaxf(v.x, v.y), fmaxf(v.z, v.w));
#pragma unroll
        for (int o = 16; o; o >>= 1) m = fmaxf(m, __shfl_xor_sync(~0u, m, o));
        if ((t & 31) == 0) wmax[t >> 5] = m;
        __syncthreads();
        const float M = fmaxf(fmaxf(fmaxf(wmax[0], wmax[1]), fmaxf(wmax[2], wmax[3])),
                              fmaxf(fmaxf(wmax[4], wmax[5]), fmaxf(wmax[6], wmax[7])));
        if (t == 0) Mrow[b] = M;
        __half2* dst = (__half2*)(Xh + (size_t)b * IN_DIM);
        dst[2 * t]     = __floats2half2_rn(v.x - M, v.y - M);
        dst[2 * t + 1] = __floats2half2_rn(v.z - M, v.w - M);
    } else {
        // W: 262144 float4s over 512 blocks; unit-stride MLP=2, 8B packed stores
        const int base = (blockIdx.x - B_DIM) * 512 + t;   // float4 index
        float4 v0 = ((const float4*)W)[base];
        float4 v1 = ((const float4*)W)[base + 256];
        __half2 a0 = __floats2half2_rn(v0.x, v0.y);
        __half2 a1 = __floats2half2_rn(v0.z, v0.w);
        __half2 b0 = __floats2half2_rn(v1.x, v1.y);
        __half2 b1 = __floats2half2_rn(v1.z, v1.w);
        uint2* dst = (uint2*)Wh;   // 8 halves per float4 = one uint2
        uint2 p0, p1;
        p0.x = *(const unsigned*)&a0;  p0.y = *(const unsigned*)&a1;
        p1.x = *(const unsigned*)&b0;  p1.y = *(const unsigned*)&b1;
        dst[base]       = p0;
        dst[base + 256] = p1;
    }
}

// ---------- main: fp16 split-K max-plus + fused tail reduction ----------
__global__ __launch_bounds__(NT)
void tropical_h(float* __restrict__ Y) {
    __shared__ __half xs[2][BMH][PADK];   //  9.2 KB
    __shared__ __half ws[2][BNH][PADK];   // 36.9 KB
    __shared__ unsigned s_last;

    const int t = threadIdx.x, lane = t & 31, wid = t >> 5;
    const int colg = (lane & 7) | ((wid & 1) << 3);    // 0..15
    const int rowg = (lane >> 3) | ((wid >> 1) << 2);  // 0..7
    const int brow = blockIdx.y * BMH;
    const int bcol = blockIdx.x * BNH;
    const int kz   = blockIdx.z;

    const int r = t >> 2;   // 0..31
    const int q = t & 3;    // 16B-quad
    const __half* Xsrc = Xh + (size_t)(brow + r) * IN_DIM + kz * KSEG + q * 8;
    const __half* Wsrc = Wh + (size_t)(bcol + r) * IN_DIM + kz * KSEG + q * 8;

    const unsigned xs_base = (unsigned)__cvta_generic_to_shared(&xs[0][0][0]);
    const unsigned ws_base = (unsigned)__cvta_generic_to_shared(&ws[0][0][0]);
    const unsigned xd = xs_base + (unsigned)(r * PADK + q * 8) * 2;
    const unsigned wd = ws_base + (unsigned)(r * PADK + q * 8) * 2;
    const unsigned XBUF   = (unsigned)(BMH * PADK) * 2;
    const unsigned WBUF   = (unsigned)(BNH * PADK) * 2;
    const unsigned WROW32 = (unsigned)(32 * PADK) * 2;

#define STAGE(c, buf) do {                                                   \
        const __half* xsp = Xsrc + (c) * BKH;                                \
        const __half* wsp = Wsrc + (c) * BKH;                                \
        CPA16(xd + (buf) * XBUF,      xsp);                                  \
        CPA16(xd + (buf) * XBUF + 64, xsp + 32);                             \
        _Pragma("unroll")                                                    \
        for (int p = 0; p < 4; ++p) {                                        \
            CPA16(wd + (buf) * WBUF + p * WROW32,      wsp + (size_t)32 * p * IN_DIM); \
            CPA16(wd + (buf) * WBUF + p * WROW32 + 64, wsp + (size_t)32 * p * IN_DIM + 32); \
        }                                                                    \
        CPA_COMMIT();                                                        \
    } while (0)

    __half2 acc[4][8];
    const __half2 ninf = __floats2half2_rn(-60000.f, -60000.f);
#pragma unroll
    for (int i = 0; i < 4; ++i)
#pragma unroll
        for (int c = 0; c < 8; ++c)
            acc[i][c] = ninf;

    STAGE(0, 0);

#pragma unroll 1
    for (int c = 0; c < NCHH; ++c) {
        if (c + 1 < NCHH) { STAGE(c + 1, (c + 1) & 1); CPA_WAIT1(); }
        else              { CPA_WAIT0(); }
        __syncthreads();

        const int buf = c & 1;
        const __half* xb = &xs[buf][0][0];
        const __half* wb = &ws[buf][0][0];

#pragma unroll 2
        for (int m = 0; m < 8; ++m) {
            uint4 xv[4], wv[8];
#pragma unroll
            for (int i = 0; i < 4; ++i)
                xv[i] = *(const uint4*)(xb + (rowg + 8 * i) * PADK + 8 * m);
#pragma unroll
            for (int j = 0; j < 8; ++j)
                wv[j] = *(const uint4*)(wb + (colg + 16 * j) * PADK + 8 * m);

            const __half2* x2 = (const __half2*)xv;   // [i*4 + p]
            const __half2* w2 = (const __half2*)wv;   // [j*4 + p]
#pragma unroll
            for (int i = 0; i < 4; ++i)
#pragma unroll
                for (int j = 0; j < 8; ++j)
#pragma unroll
                    for (int p = 0; p < 4; ++p)
                        acc[i][j] = __hmax2(acc[i][j],
                                            __hadd2(x2[i * 4 + p], w2[j * 4 + p]));
        }

        if (c + 1 < NCHH) __syncthreads();   // protect buf before restage
    }

    // ---- epilogue: pair-reduce, write half partials ----
    __half* out = &g_parth[kz][0];
#pragma unroll
    for (int i = 0; i < 4; ++i)
#pragma unroll
        for (int j = 0; j < 8; ++j) {
            const __half2 a = acc[i][j];
            out[(size_t)(brow + rowg + 8 * i) * OUT_DIM + bcol + colg + 16 * j] =
                __hmax(__low2half(a), __high2half(a));
        }

    // ---- last-block-done tail reduction (replaces combine kernel) ----
    __threadfence();                       // release partial stores
    __syncthreads();                       // all threads' stores fenced
    if (t == 0) {
        const unsigned old = atomicAdd(&g_cnt[blockIdx.y * 8 + blockIdx.x], 1u);
        s_last = ((old & (SPLITK - 1)) == (SPLITK - 1)) ? 1u : 0u;
    }
    __syncthreads();
    if (s_last) {
        __threadfence();                   // acquire side
        // tile = rows [brow, brow+32), cols [bcol, bcol+128) = 512 chunks of 8
#pragma unroll
        for (int cc = 0; cc < 4; ++cc) {
            const int chunk = t + cc * NT;          // 0..511
            const int row   = chunk >> 4;           // 0..31
            const int col8  = (chunk & 15) << 3;    // 0..120
            const size_t h_idx = (size_t)(brow + row) * OUT_DIM + bcol + col8;
            const size_t v_idx = h_idx >> 3;        // uint4 (8 halves) index
            uint4 v = ((const uint4*)g_parth[0])[v_idx];
            __half2 m0 = ((const __half2*)&v)[0], m1 = ((const __half2*)&v)[1];
            __half2 m2 = ((const __half2*)&v)[2], m3 = ((const __half2*)&v)[3];
#pragma unroll
            for (int s = 1; s < SPLITK; ++s) {
                uint4 u = ((const uint4*)g_parth[s])[v_idx];
                m0 = __hmax2(m0, ((const __half2*)&u)[0]);
                m1 = __hmax2(m1, ((const __half2*)&u)[1]);
                m2 = __hmax2(m2, ((const __half2*)&u)[2]);
                m3 = __hmax2(m3, ((const __half2*)&u)[3]);
            }
            const float M = Mrow[brow + row];
            float2 f0 = __half22float2(m0), f1 = __half22float2(m1);
            float2 f2 = __half22float2(m2), f3 = __half22float2(m3);
            float4* Yo = (float4*)(Y + h_idx);
            Yo[0] = make_float4(f0.x + M, f0.y + M, f1.x + M, f1.y + M);
            Yo[1] = make_float4(f2.x + M, f2.y + M, f3.x + M, f3.y + M);
        }
    }
#undef STAGE
}

extern "C" void kernel_launch(void* const* d_in, const int* in_sizes, int n_in,
                              void* d_out, int out_size) {
    const float* X = (const float*)d_in[0];   // [512, 1024]
    const float* W = (const float*)d_in[1];   // [1024, 1024]
    float* Y = (float*)d_out;                 // [512, 1024]
    (void)in_sizes; (void)n_in; (void)out_size;

    prep_xw<<<B_DIM + 512, 256>>>(X, W);             // 1024 blocks

    dim3 grid(OUT_DIM / BNH, B_DIM / BMH, SPLITK);   // (8, 16, 8) = 1024 blocks
    tropical_h<<<grid, NT>>>(Y);
}

// round 12
// speedup vs baseline: 1.2406x; 1.2406x over previous
#include <cuda_runtime.h>
#include <cuda_fp16.h>
#include <cstdint>

// Tropical (max-plus) matmul: Y[b, j] = max_i (X[b, i] + W[j, i])
// fp16 path with per-row fp32 shift:
//   M_b = max_i X[b,i];  Xh = half(X - M_b);  Wh = half(W)
//   Y' = max-plus in packed fp16 (HADD2/HMNMX2 paired over k);  Y = Y' + M_b.
// Measured rel_err ~1.3e-6.
//
// R11: revert R10's fused tail (threadfence = CCTL.IVALL L1D flush per
// block -> issue collapsed to 50%). Back to R9 structure; single change:
// BKH 64->32 halves (PADK=40) halving smem 46->25.6KB so residency rises
// 4->5 blocks/SM (+25% warps for latency hiding). Double buffer kept.

#define B_DIM   512
#define IN_DIM  1024
#define OUT_DIM 1024

#define SPLITK  8
#define KSEG    (IN_DIM / SPLITK)   // 128
#define BKH     32                  // halves per chunk
#define NCHH    (KSEG / BKH)        // 4
#define BMH     32
#define BNH     128
#define PADK    40                  // padded halves per smem row (80 B)
#define NT      128

__device__ __half Xh[B_DIM * IN_DIM];
__device__ __half Wh[OUT_DIM * IN_DIM];
__device__ float  Mrow[B_DIM];
__device__ __half g_parth[SPLITK][B_DIM * OUT_DIM];   // 8 MB

#define CPA16(dst_u32, src_ptr) \
    asm volatile("cp.async.cg.shared.global [%0], [%1], 16;" \
                 :: "r"(dst_u32), "l"(src_ptr))
#define CPA_COMMIT() asm volatile("cp.async.commit_group;")
#define CPA_WAIT1()  asm volatile("cp.async.wait_group 1;")
#define CPA_WAIT0()  asm volatile("cp.async.wait_group 0;")

// ---------- fused prep: blocks [0,512) shift+cvt X; [512,1024) cvt W ----------
__global__ __launch_bounds__(256)
void prep_xw(const float* __restrict__ X, const float* __restrict__ W) {
    const int t = threadIdx.x;
    if (blockIdx.x < B_DIM) {
        __shared__ float wmax[8];
        const int b = blockIdx.x;
        float4 v = ((const float4*)(X + (size_t)b * IN_DIM))[t];
        float m = fmaxf(fmaxf(v.x, v.y), fmaxf(v.z, v.w));
#pragma unroll
        for (int o = 16; o; o >>= 1) m = fmaxf(m, __shfl_xor_sync(~0u, m, o));
        if ((t & 31) == 0) wmax[t >> 5] = m;
        __syncthreads();
        const float M = fmaxf(fmaxf(fmaxf(wmax[0], wmax[1]), fmaxf(wmax[2], wmax[3])),
                              fmaxf(fmaxf(wmax[4], wmax[5]), fmaxf(wmax[6], wmax[7])));
        if (t == 0) Mrow[b] = M;
        __half2* dst = (__half2*)(Xh + (size_t)b * IN_DIM);
        dst[2 * t]     = __floats2half2_rn(v.x - M, v.y - M);
        dst[2 * t + 1] = __floats2half2_rn(v.z - M, v.w - M);
    } else {
        // W: 262144 float4s over 512 blocks; unit-stride MLP=2, 8B packed stores
        const int base = (blockIdx.x - B_DIM) * 512 + t;   // float4 index
        float4 v0 = ((const float4*)W)[base];
        float4 v1 = ((const float4*)W)[base + 256];
        __half2 a0 = __floats2half2_rn(v0.x, v0.y);
        __half2 a1 = __floats2half2_rn(v0.z, v0.w);
        __half2 b0 = __floats2half2_rn(v1.x, v1.y);
        __half2 b1 = __floats2half2_rn(v1.z, v1.w);
        uint2* dst = (uint2*)Wh;   // 8 halves per float4 = one uint2
        uint2 p0, p1;
        p0.x = *(const unsigned*)&a0;  p0.y = *(const unsigned*)&a1;
        p1.x = *(const unsigned*)&b0;  p1.y = *(const unsigned*)&b1;
        dst[base]       = p0;
        dst[base + 256] = p1;
    }
}

// ---------- main: fp16 split-K max-plus, BK=32 double-buffered ----------
__global__ __launch_bounds__(NT)
void tropical_h() {
    __shared__ __half xs[2][BMH][PADK];   //  5.0 KB
    __shared__ __half ws[2][BNH][PADK];   // 20.0 KB

    const int t = threadIdx.x, lane = t & 31, wid = t >> 5;
    const int colg = (lane & 7) | ((wid & 1) << 3);    // 0..15
    const int rowg = (lane >> 3) | ((wid >> 1) << 2);  // 0..7
    const int brow = blockIdx.y * BMH;
    const int bcol = blockIdx.x * BNH;
    const int kz   = blockIdx.z;

    const int r = t >> 2;   // 0..31
    const int q = t & 3;    // 16B-quad within 64B chunk row
    const __half* Xsrc = Xh + (size_t)(brow + r) * IN_DIM + kz * KSEG + q * 8;
    const __half* Wsrc = Wh + (size_t)(bcol + r) * IN_DIM + kz * KSEG + q * 8;

    const unsigned xs_base = (unsigned)__cvta_generic_to_shared(&xs[0][0][0]);
    const unsigned ws_base = (unsigned)__cvta_generic_to_shared(&ws[0][0][0]);
    const unsigned xd = xs_base + (unsigned)(r * PADK + q * 8) * 2;
    const unsigned wd = ws_base + (unsigned)(r * PADK + q * 8) * 2;
    const unsigned XBUF   = (unsigned)(BMH * PADK) * 2;
    const unsigned WBUF   = (unsigned)(BNH * PADK) * 2;
    const unsigned WROW32 = (unsigned)(32 * PADK) * 2;

// per chunk: X 32 rows x 64B -> 1 quad/thread; W 128 rows x 64B -> 4 quads/thread
#define STAGE(c, buf) do {                                                   \
        const __half* xsp = Xsrc + (c) * BKH;                                \
        const __half* wsp = Wsrc + (c) * BKH;                                \
        CPA16(xd + (buf) * XBUF, xsp);                                       \
        _Pragma("unroll")                                                    \
        for (int p = 0; p < 4; ++p)                                          \
            CPA16(wd + (buf) * WBUF + p * WROW32, wsp + (size_t)32 * p * IN_DIM); \
        CPA_COMMIT();                                                        \
    } while (0)

    __half2 acc[4][8];
    const __half2 ninf = __floats2half2_rn(-60000.f, -60000.f);
#pragma unroll
    for (int i = 0; i < 4; ++i)
#pragma unroll
        for (int c = 0; c < 8; ++c)
            acc[i][c] = ninf;

    STAGE(0, 0);

#pragma unroll 1
    for (int c = 0; c < NCHH; ++c) {
        if (c + 1 < NCHH) { STAGE(c + 1, (c + 1) & 1); CPA_WAIT1(); }
        else              { CPA_WAIT0(); }
        __syncthreads();

        const int buf = c & 1;
        const __half* xb = &xs[buf][0][0];
        const __half* wb = &ws[buf][0][0];

#pragma unroll 2
        for (int m = 0; m < 4; ++m) {
            uint4 xv[4], wv[8];
#pragma unroll
            for (int i = 0; i < 4; ++i)
                xv[i] = *(const uint4*)(xb + (rowg + 8 * i) * PADK + 8 * m);
#pragma unroll
            for (int j = 0; j < 8; ++j)
                wv[j] = *(const uint4*)(wb + (colg + 16 * j) * PADK + 8 * m);

            const __half2* x2 = (const __half2*)xv;   // [i*4 + p]
            const __half2* w2 = (const __half2*)wv;   // [j*4 + p]
#pragma unroll
            for (int i = 0; i < 4; ++i)
#pragma unroll
                for (int j = 0; j < 8; ++j)
#pragma unroll
                    for (int p = 0; p < 4; ++p)
                        acc[i][j] = __hmax2(acc[i][j],
                                            __hadd2(x2[i * 4 + p], w2[j * 4 + p]));
        }

        if (c + 1 < NCHH) __syncthreads();   // protect buf before restage
    }

    // epilogue: pair-reduce, write half partials
    __half* out = &g_parth[kz][0];
#pragma unroll
    for (int i = 0; i < 4; ++i)
#pragma unroll
        for (int j = 0; j < 8; ++j) {
            const __half2 a = acc[i][j];
            out[(size_t)(brow + rowg + 8 * i) * OUT_DIM + bcol + colg + 16 * j] =
                __hmax(__low2half(a), __high2half(a));
        }
#undef STAGE
}

// ---------- combine: 8-way packed max + add back row shift ----------
__global__ __launch_bounds__(256)
void combine_max8(float* __restrict__ Y) {
    const int i = blockIdx.x * 256 + threadIdx.x;   // 8-half chunk index
    const float M = Mrow[(i << 3) >> 10];           // 8 halves stay in one row
    uint4 v = ((const uint4*)g_parth[0])[i];
    __half2 m0 = ((const __half2*)&v)[0], m1 = ((const __half2*)&v)[1];
    __half2 m2 = ((const __half2*)&v)[2], m3 = ((const __half2*)&v)[3];
#pragma unroll
    for (int s = 1; s < SPLITK; ++s) {
        uint4 u = ((const uint4*)g_parth[s])[i];
        m0 = __hmax2(m0, ((const __half2*)&u)[0]);
        m1 = __hmax2(m1, ((const __half2*)&u)[1]);
        m2 = __hmax2(m2, ((const __half2*)&u)[2]);
        m3 = __hmax2(m3, ((const __half2*)&u)[3]);
    }
    float4* Yo = (float4*)(Y + ((size_t)i << 3));
    float2 f0 = __half22float2(m0), f1 = __half22float2(m1);
    float2 f2 = __half22float2(m2), f3 = __half22float2(m3);
    Yo[0] = make_float4(f0.x + M, f0.y + M, f1.x + M, f1.y + M);
    Yo[1] = make_float4(f2.x + M, f2.y + M, f3.x + M, f3.y + M);
}

extern "C" void kernel_launch(void* const* d_in, const int* in_sizes, int n_in,
                              void* d_out, int out_size) {
    const float* X = (const float*)d_in[0];   // [512, 1024]
    const float* W = (const float*)d_in[1];   // [1024, 1024]
    float* Y = (float*)d_out;                 // [512, 1024]
    (void)in_sizes; (void)n_in; (void)out_size;

    prep_xw<<<B_DIM + 512, 256>>>(X, W);             // 1024 blocks

    dim3 grid(OUT_DIM / BNH, B_DIM / BMH, SPLITK);   // (8, 16, 8) = 1024 blocks
    tropical_h<<<grid, NT>>>();

    combine_max8<<<B_DIM * OUT_DIM / 8 / 256, 256>>>(Y);   // 256 blocks
}

// round 13
// speedup vs baseline: 1.5772x; 1.2713x over previous
#include <cuda_runtime.h>
#include <cuda_fp16.h>
#include <cstdint>

// Tropical (max-plus) matmul: Y[b, j] = max_i (X[b, i] + W[j, i])
// fp16 path with per-row fp32 shift:
//   M_b = max_i X[b,i];  Xh = half(X - M_b);  Wh = half(W)
//   Y' = max-plus in packed fp16 (HADD2/HMNMX2 paired over k);  Y = Y' + M_b.
// Measured rel_err ~1.3e-6.
//
// R13: back to the R9 pipeline (BKH=64, 2 chunks, W double-buffered —
// R11's BKH=32 doubled barrier count and halved the latency-hiding window,
// regressing 8us). Single change vs R9: X's K-segment (32x128 halves) is
// staged ONCE into a single buffer (it's read-only across both chunks),
// cutting smem 46.1 -> 44.5KB so residency rises 4 -> 5 blocks/SM.

#define B_DIM   512
#define IN_DIM  1024
#define OUT_DIM 1024

#define SPLITK  8
#define KSEG    (IN_DIM / SPLITK)   // 128
#define BKH     64                  // halves per W chunk
#define NCHH    (KSEG / BKH)        // 2
#define BMH     32
#define BNH     128
#define PADK    72                  // W smem row pad (halves)
#define XPAD    136                 // X smem row pad (halves, full KSEG row)
#define NT      128

__device__ __half Xh[B_DIM * IN_DIM];
__device__ __half Wh[OUT_DIM * IN_DIM];
__device__ float  Mrow[B_DIM];
__device__ __half g_parth[SPLITK][B_DIM * OUT_DIM];   // 8 MB

#define CPA16(dst_u32, src_ptr) \
    asm volatile("cp.async.cg.shared.global [%0], [%1], 16;" \
                 :: "r"(dst_u32), "l"(src_ptr))
#define CPA_COMMIT() asm volatile("cp.async.commit_group;")
#define CPA_WAIT1()  asm volatile("cp.async.wait_group 1;")
#define CPA_WAIT0()  asm volatile("cp.async.wait_group 0;")

// ---------- fused prep: blocks [0,512) shift+cvt X; [512,1024) cvt W ----------
__global__ __launch_bounds__(256)
void prep_xw(const float* __restrict__ X, const float* __restrict__ W) {
    const int t = threadIdx.x;
    if (blockIdx.x < B_DIM) {
        __shared__ float wmax[8];
        const int b = blockIdx.x;
        float4 v = ((const float4*)(X + (size_t)b * IN_DIM))[t];
        float m = fmaxf(fmaxf(v.x, v.y), fmaxf(v.z, v.w));
#pragma unroll
        for (int o = 16; o; o >>= 1) m = fmaxf(m, __shfl_xor_sync(~0u, m, o));
        if ((t & 31) == 0) wmax[t >> 5] = m;
        __syncthreads();
        const float M = fmaxf(fmaxf(fmaxf(wmax[0], wmax[1]), fmaxf(wmax[2], wmax[3])),
                              fmaxf(fmaxf(wmax[4], wmax[5]), fmaxf(wmax[6], wmax[7])));
        if (t == 0) Mrow[b] = M;
        __half2* dst = (__half2*)(Xh + (size_t)b * IN_DIM);
        dst[2 * t]     = __floats2half2_rn(v.x - M, v.y - M);
        dst[2 * t + 1] = __floats2half2_rn(v.z - M, v.w - M);
    } else {
        // W: 262144 float4s over 512 blocks; unit-stride MLP=2, 8B packed stores
        const int base = (blockIdx.x - B_DIM) * 512 + t;   // float4 index
        float4 v0 = ((const float4*)W)[base];
        float4 v1 = ((const float4*)W)[base + 256];
        __half2 a0 = __floats2half2_rn(v0.x, v0.y);
        __half2 a1 = __floats2half2_rn(v0.z, v0.w);
        __half2 b0 = __floats2half2_rn(v1.x, v1.y);
        __half2 b1 = __floats2half2_rn(v1.z, v1.w);
        uint2* dst = (uint2*)Wh;
        uint2 p0, p1;
        p0.x = *(const unsigned*)&a0;  p0.y = *(const unsigned*)&a1;
        p1.x = *(const unsigned*)&b0;  p1.y = *(const unsigned*)&b1;
        dst[base]       = p0;
        dst[base + 256] = p1;
    }
}

// ---------- main: fp16 split-K max-plus ----------
__global__ __launch_bounds__(NT)
void tropical_h() {
    __shared__ __half xs[BMH][XPAD];      //  8.5 KB (single buffer, full KSEG)
    __shared__ __half ws[2][BNH][PADK];   // 36.9 KB (double buffered)

    const int t = threadIdx.x, lane = t & 31, wid = t >> 5;
    const int colg = (lane & 7) | ((wid & 1) << 3);    // 0..15
    const int rowg = (lane >> 3) | ((wid >> 1) << 2);  // 0..7
    const int brow = blockIdx.y * BMH;
    const int bcol = blockIdx.x * BNH;
    const int kz   = blockIdx.z;

    const int r = t >> 2;   // 0..31
    const int q = t & 3;    // 16B-quad
    const __half* Xsrc = Xh + (size_t)(brow + r) * IN_DIM + kz * KSEG;
    const __half* Wsrc = Wh + (size_t)(bcol + r) * IN_DIM + kz * KSEG + q * 8;

    const unsigned xs_base = (unsigned)__cvta_generic_to_shared(&xs[0][0]);
    const unsigned ws_base = (unsigned)__cvta_generic_to_shared(&ws[0][0][0]);
    const unsigned wd = ws_base + (unsigned)(r * PADK + q * 8) * 2;
    const unsigned WBUF   = (unsigned)(BNH * PADK) * 2;
    const unsigned WROW32 = (unsigned)(32 * PADK) * 2;

#define STAGE_W(c, buf) do {                                                 \
        const __half* wsp = Wsrc + (c) * BKH;                                \
        _Pragma("unroll")                                                    \
        for (int p = 0; p < 4; ++p) {                                        \
            CPA16(wd + (buf) * WBUF + p * WROW32,      wsp + (size_t)32 * p * IN_DIM); \
            CPA16(wd + (buf) * WBUF + p * WROW32 + 64, wsp + (size_t)32 * p * IN_DIM + 32); \
        }                                                                    \
        CPA_COMMIT();                                                        \
    } while (0)

    // stage ALL of X's K-segment once: 32 rows x 256B, quads q+4p
    {
        const unsigned xd = xs_base + (unsigned)(r * XPAD) * 2;
#pragma unroll
        for (int p = 0; p < 4; ++p)
            CPA16(xd + (unsigned)(q + 4 * p) * 16, Xsrc + (q + 4 * p) * 8);
    }
    STAGE_W(0, 0);   // X + W chunk 0 share commit group 0

    __half2 acc[4][8];
    const __half2 ninf = __floats2half2_rn(-60000.f, -60000.f);
#pragma unroll
    for (int i = 0; i < 4; ++i)
#pragma unroll
        for (int c = 0; c < 8; ++c)
            acc[i][c] = ninf;

#pragma unroll 1
    for (int c = 0; c < NCHH; ++c) {
        if (c + 1 < NCHH) { STAGE_W(c + 1, (c + 1) & 1); CPA_WAIT1(); }
        else              { CPA_WAIT0(); }
        __syncthreads();

        const int buf = c & 1;
        const __half* wb = &ws[buf][0][0];
        const __half* xb = &xs[0][0];

#pragma unroll 2
        for (int m = 0; m < 8; ++m) {
            const int xq = c * 8 + m;    // quad index within KSEG
            uint4 xv[4], wv[8];
#pragma unroll
            for (int i = 0; i < 4; ++i)
                xv[i] = *(const uint4*)(xb + (rowg + 8 * i) * XPAD + 8 * xq);
#pragma unroll
            for (int j = 0; j < 8; ++j)
                wv[j] = *(const uint4*)(wb + (colg + 16 * j) * PADK + 8 * m);

            const __half2* x2 = (const __half2*)xv;   // [i*4 + p]
            const __half2* w2 = (const __half2*)wv;   // [j*4 + p]
#pragma unroll
            for (int i = 0; i < 4; ++i)
#pragma unroll
                for (int j = 0; j < 8; ++j)
#pragma unroll
                    for (int p = 0; p < 4; ++p)
                        acc[i][j] = __hmax2(acc[i][j],
                                            __hadd2(x2[i * 4 + p], w2[j * 4 + p]));
        }

        if (c + 1 < NCHH) __syncthreads();   // protect W buf before restage
    }

    // epilogue: pair-reduce, write half partials
    __half* out = &g_parth[kz][0];
#pragma unroll
    for (int i = 0; i < 4; ++i)
#pragma unroll
        for (int j = 0; j < 8; ++j) {
            const __half2 a = acc[i][j];
            out[(size_t)(brow + rowg + 8 * i) * OUT_DIM + bcol + colg + 16 * j] =
                __hmax(__low2half(a), __high2half(a));
        }
#undef STAGE_W
}

// ---------- combine: 8-way packed max + add back row shift ----------
__global__ __launch_bounds__(256)
void combine_max8(float* __restrict__ Y) {
    const int i = blockIdx.x * 256 + threadIdx.x;   // 8-half chunk index
    const float M = Mrow[(i << 3) >> 10];           // 8 halves stay in one row
    uint4 v = ((const uint4*)g_parth[0])[i];
    __half2 m0 = ((const __half2*)&v)[0], m1 = ((const __half2*)&v)[1];
    __half2 m2 = ((const __half2*)&v)[2], m3 = ((const __half2*)&v)[3];
#pragma unroll
    for (int s = 1; s < SPLITK; ++s) {
        uint4 u = ((const uint4*)g_parth[s])[i];
        m0 = __hmax2(m0, ((const __half2*)&u)[0]);
        m1 = __hmax2(m1, ((const __half2*)&u)[1]);
        m2 = __hmax2(m2, ((const __half2*)&u)[2]);
        m3 = __hmax2(m3, ((const __half2*)&u)[3]);
    }
    float4* Yo = (float4*)(Y + ((size_t)i << 3));
    float2 f0 = __half22float2(m0), f1 = __half22float2(m1);
    float2 f2 = __half22float2(m2), f3 = __half22float2(m3);
    Yo[0] = make_float4(f0.x + M, f0.y + M, f1.x + M, f1.y + M);
    Yo[1] = make_float4(f2.x + M, f2.y + M, f3.x + M, f3.y + M);
}

extern "C" void kernel_launch(void* const* d_in, const int* in_sizes, int n_in,
                              void* d_out, int out_size) {
    const float* X = (const float*)d_in[0];   // [512, 1024]
    const float* W = (const float*)d_in[1];   // [1024, 1024]
    float* Y = (float*)d_out;                 // [512, 1024]
    (void)in_sizes; (void)n_in; (void)out_size;

    prep_xw<<<B_DIM + 512, 256>>>(X, W);             // 1024 blocks

    dim3 grid(OUT_DIM / BNH, B_DIM / BMH, SPLITK);   // (8, 16, 8) = 1024 blocks
    tropical_h<<<grid, NT>>>();

    combine_max8<<<B_DIM * OUT_DIM / 8 / 256, 256>>>(Y);   // 256 blocks
}

// round 14
// speedup vs baseline: 1.5788x; 1.0010x over previous
#include <cuda_runtime.h>
#include <cuda_fp16.h>
#include <cstdint>

// Tropical (max-plus) matmul: Y[b, j] = max_i (X[b, i] + W[j, i])
// fp16 path with per-row fp32 shift:
//   M_b = max_i X[b,i];  Xh = half(X - M_b);  Wh = half(W)
//   Y' = max-plus in packed fp16 (HADD2/HMNMX2 paired over k);  Y = Y' + M_b.
// Measured rel_err ~1.3e-6.
//
// R14: R13 kernels unchanged; add PDL (programmatic dependent launch) on
// prep->main and main->combine so dependent grids launch/ramp while the
// predecessor drains. All dependent-data reads sit after griddepcontrol.wait.

#define B_DIM   512
#define IN_DIM  1024
#define OUT_DIM 1024

#define SPLITK  8
#define KSEG    (IN_DIM / SPLITK)   // 128
#define BKH     64                  // halves per W chunk
#define NCHH    (KSEG / BKH)        // 2
#define BMH     32
#define BNH     128
#define PADK    72                  // W smem row pad (halves)
#define XPAD    136                 // X smem row pad (halves, full KSEG row)
#define NT      128

__device__ __half Xh[B_DIM * IN_DIM];
__device__ __half Wh[OUT_DIM * IN_DIM];
__device__ float  Mrow[B_DIM];
__device__ __half g_parth[SPLITK][B_DIM * OUT_DIM];   // 8 MB

#define CPA16(dst_u32, src_ptr) \
    asm volatile("cp.async.cg.shared.global [%0], [%1], 16;" \
                 :: "r"(dst_u32), "l"(src_ptr))
#define CPA_COMMIT() asm volatile("cp.async.commit_group;")
#define CPA_WAIT1()  asm volatile("cp.async.wait_group 1;")
#define CPA_WAIT0()  asm volatile("cp.async.wait_group 0;")

#define GRID_WAIT()       asm volatile("griddepcontrol.wait;" ::: "memory")
#define GRID_LAUNCH_DEP() asm volatile("griddepcontrol.launch_dependents;" ::: "memory")

// ---------- fused prep: blocks [0,512) shift+cvt X; [512,1024) cvt W ----------
__global__ __launch_bounds__(256)
void prep_xw(const float* __restrict__ X, const float* __restrict__ W) {
    const int t = threadIdx.x;
    if (blockIdx.x < B_DIM) {
        __shared__ float wmax[8];
        const int b = blockIdx.x;
        float4 v = ((const float4*)(X + (size_t)b * IN_DIM))[t];
        float m = fmaxf(fmaxf(v.x, v.y), fmaxf(v.z, v.w));
#pragma unroll
        for (int o = 16; o; o >>= 1) m = fmaxf(m, __shfl_xor_sync(~0u, m, o));
        if ((t & 31) == 0) wmax[t >> 5] = m;
        __syncthreads();
        const float M = fmaxf(fmaxf(fmaxf(wmax[0], wmax[1]), fmaxf(wmax[2], wmax[3])),
                              fmaxf(fmaxf(wmax[4], wmax[5]), fmaxf(wmax[6], wmax[7])));
        if (t == 0) Mrow[b] = M;
        __half2* dst = (__half2*)(Xh + (size_t)b * IN_DIM);
        dst[2 * t]     = __floats2half2_rn(v.x - M, v.y - M);
        dst[2 * t + 1] = __floats2half2_rn(v.z - M, v.w - M);
    } else {
        // W: 262144 float4s over 512 blocks; unit-stride MLP=2, 8B packed stores
        const int base = (blockIdx.x - B_DIM) * 512 + t;   // float4 index
        float4 v0 = ((const float4*)W)[base];
        float4 v1 = ((const float4*)W)[base + 256];
        __half2 a0 = __floats2half2_rn(v0.x, v0.y);
        __half2 a1 = __floats2half2_rn(v0.z, v0.w);
        __half2 b0 = __floats2half2_rn(v1.x, v1.y);
        __half2 b1 = __floats2half2_rn(v1.z, v1.w);
        uint2* dst = (uint2*)Wh;
        uint2 p0, p1;
        p0.x = *(const unsigned*)&a0;  p0.y = *(const unsigned*)&a1;
        p1.x = *(const unsigned*)&b0;  p1.y = *(const unsigned*)&b1;
        dst[base]       = p0;
        dst[base + 256] = p1;
    }
    GRID_LAUNCH_DEP();   // this block's Xh/Wh/Mrow stores are done
}

// ---------- main: fp16 split-K max-plus ----------
__global__ __launch_bounds__(NT)
void tropical_h() {
    __shared__ __half xs[BMH][XPAD];      //  8.5 KB (single buffer, full KSEG)
    __shared__ __half ws[2][BNH][PADK];   // 36.9 KB (double buffered)

    const int t = threadIdx.x, lane = t & 31, wid = t >> 5;
    const int colg = (lane & 7) | ((wid & 1) << 3);    // 0..15
    const int rowg = (lane >> 3) | ((wid >> 1) << 2);  // 0..7
    const int brow = blockIdx.y * BMH;
    const int bcol = blockIdx.x * BNH;
    const int kz   = blockIdx.z;

    const int r = t >> 2;   // 0..31
    const int q = t & 3;    // 16B-quad
    const __half* Xsrc = Xh + (size_t)(brow + r) * IN_DIM + kz * KSEG;
    const __half* Wsrc = Wh + (size_t)(bcol + r) * IN_DIM + kz * KSEG + q * 8;

    const unsigned xs_base = (unsigned)__cvta_generic_to_shared(&xs[0][0]);
    const unsigned ws_base = (unsigned)__cvta_generic_to_shared(&ws[0][0][0]);
    const unsigned wd = ws_base + (unsigned)(r * PADK + q * 8) * 2;
    const unsigned WBUF   = (unsigned)(BNH * PADK) * 2;
    const unsigned WROW32 = (unsigned)(32 * PADK) * 2;

#define STAGE_W(c, buf) do {                                                 \
        const __half* wsp = Wsrc + (c) * BKH;                                \
        _Pragma("unroll")                                                    \
        for (int p = 0; p < 4; ++p) {                                        \
            CPA16(wd + (buf) * WBUF + p * WROW32,      wsp + (size_t)32 * p * IN_DIM); \
            CPA16(wd + (buf) * WBUF + p * WROW32 + 64, wsp + (size_t)32 * p * IN_DIM + 32); \
        }                                                                    \
        CPA_COMMIT();                                                        \
    } while (0)

    // PDL: wait for prep's stores before the first dependent-data read
    GRID_WAIT();

    // stage ALL of X's K-segment once: 32 rows x 256B, quads q+4p
    {
        const unsigned xd = xs_base + (unsigned)(r * XPAD) * 2;
#pragma unroll
        for (int p = 0; p < 4; ++p)
            CPA16(xd + (unsigned)(q + 4 * p) * 16, Xsrc + (q + 4 * p) * 8);
    }
    STAGE_W(0, 0);   // X + W chunk 0 share commit group 0

    __half2 acc[4][8];
    const __half2 ninf = __floats2half2_rn(-60000.f, -60000.f);
#pragma unroll
    for (int i = 0; i < 4; ++i)
#pragma unroll
        for (int c = 0; c < 8; ++c)
            acc[i][c] = ninf;

#pragma unroll 1
    for (int c = 0; c < NCHH; ++c) {
        if (c + 1 < NCHH) { STAGE_W(c + 1, (c + 1) & 1); CPA_WAIT1(); }
        else              { CPA_WAIT0(); }
        __syncthreads();

        const int buf = c & 1;
        const __half* wb = &ws[buf][0][0];
        const __half* xb = &xs[0][0];

#pragma unroll 2
        for (int m = 0; m < 8; ++m) {
            const int xq = c * 8 + m;    // quad index within KSEG
            uint4 xv[4], wv[8];
#pragma unroll
            for (int i = 0; i < 4; ++i)
                xv[i] = *(const uint4*)(xb + (rowg + 8 * i) * XPAD + 8 * xq);
#pragma unroll
            for (int j = 0; j < 8; ++j)
                wv[j] = *(const uint4*)(wb + (colg + 16 * j) * PADK + 8 * m);

            const __half2* x2 = (const __half2*)xv;   // [i*4 + p]
            const __half2* w2 = (const __half2*)wv;   // [j*4 + p]
#pragma unroll
            for (int i = 0; i < 4; ++i)
#pragma unroll
                for (int j = 0; j < 8; ++j)
#pragma unroll
                    for (int p = 0; p < 4; ++p)
                        acc[i][j] = __hmax2(acc[i][j],
                                            __hadd2(x2[i * 4 + p], w2[j * 4 + p]));
        }

        if (c + 1 < NCHH) __syncthreads();   // protect W buf before restage
    }

    // epilogue: pair-reduce, write half partials
    __half* out = &g_parth[kz][0];
#pragma unroll
    for (int i = 0; i < 4; ++i)
#pragma unroll
        for (int j = 0; j < 8; ++j) {
            const __half2 a = acc[i][j];
            out[(size_t)(brow + rowg + 8 * i) * OUT_DIM + bcol + colg + 16 * j] =
                __hmax(__low2half(a), __high2half(a));
        }
    GRID_LAUNCH_DEP();   // this block's partials are stored
#undef STAGE_W
}

// ---------- combine: 8-way packed max + add back row shift ----------
__global__ __launch_bounds__(256)
void combine_max8(float* __restrict__ Y) {
    const int i = blockIdx.x * 256 + threadIdx.x;   // 8-half chunk index

    // PDL: all global reads (g_parth AND Mrow) after the wait — combine's
    // edge is with main; prep's stores are visible transitively.
    GRID_WAIT();

    const float M = Mrow[(i << 3) >> 10];           // 8 halves stay in one row
    uint4 v = ((const uint4*)g_parth[0])[i];
    __half2 m0 = ((const __half2*)&v)[0], m1 = ((const __half2*)&v)[1];
    __half2 m2 = ((const __half2*)&v)[2], m3 = ((const __half2*)&v)[3];
#pragma unroll
    for (int s = 1; s < SPLITK; ++s) {
        uint4 u = ((const uint4*)g_parth[s])[i];
        m0 = __hmax2(m0, ((const __half2*)&u)[0]);
        m1 = __hmax2(m1, ((const __half2*)&u)[1]);
        m2 = __hmax2(m2, ((const __half2*)&u)[2]);
        m3 = __hmax2(m3, ((const __half2*)&u)[3]);
    }
    float4* Yo = (float4*)(Y + ((size_t)i << 3));
    float2 f0 = __half22float2(m0), f1 = __half22float2(m1);
    float2 f2 = __half22float2(m2), f3 = __half22float2(m3);
    Yo[0] = make_float4(f0.x + M, f0.y + M, f1.x + M, f1.y + M);
    Yo[1] = make_float4(f2.x + M, f2.y + M, f3.x + M, f3.y + M);
}

extern "C" void kernel_launch(void* const* d_in, const int* in_sizes, int n_in,
                              void* d_out, int out_size) {
    const float* X = (const float*)d_in[0];   // [512, 1024]
    const float* W = (const float*)d_in[1];   // [1024, 1024]
    float* Y = (float*)d_out;                 // [512, 1024]
    (void)in_sizes; (void)n_in; (void)out_size;

    prep_xw<<<B_DIM + 512, 256>>>(X, W);             // 1024 blocks

    // main: PDL-dependent on prep
    {
        cudaLaunchConfig_t cfg = {};
        cfg.gridDim  = dim3(OUT_DIM / BNH, B_DIM / BMH, SPLITK);  // (8,16,8)
        cfg.blockDim = dim3(NT, 1, 1);
        cfg.dynamicSmemBytes = 0;
        cfg.stream = 0;
        cudaLaunchAttribute attr[1];
        attr[0].id = cudaLaunchAttributeProgrammaticStreamSerialization;
        attr[0].val.programmaticStreamSerializationAllowed = 1;
        cfg.attrs = attr;
        cfg.numAttrs = 1;
        cudaLaunchKernelEx(&cfg, tropical_h);
    }

    // combine: PDL-dependent on main
    {
        cudaLaunchConfig_t cfg = {};
        cfg.gridDim  = dim3(B_DIM * OUT_DIM / 8 / 256, 1, 1);     // 256 blocks
        cfg.blockDim = dim3(256, 1, 1);
        cfg.dynamicSmemBytes = 0;
        cfg.stream = 0;
        cudaLaunchAttribute attr[1];
        attr[0].id = cudaLaunchAttributeProgrammaticStreamSerialization;
        attr[0].val.programmaticStreamSerializationAllowed = 1;
        cfg.attrs = attr;
        cfg.numAttrs = 1;
        cudaLaunchKernelEx(&cfg, combine_max8, Y);
    }
}